// round 3
// baseline (speedup 1.0000x reference)
#include <cuda_runtime.h>
#include <cuda_bf16.h>

#define B 2
#define N 8192
#define M 8192
#define D 64
#define KNN 16
#define QTOT (B * M)

// Scratch (allocation-free: __device__ globals)
__device__ float g_f[B * N * D];        // projected features, 4MB
__device__ int   g_idx[B * M * KNN];    // knn indices, 512KB

// ---------------------------------------------------------------------------
// Kernel 1: f = feature1 @ Wp + bp    [B*N, 64] x [64, 64]
// ---------------------------------------------------------------------------
__global__ __launch_bounds__(256) void proj_kernel(
    const float* __restrict__ feat, const float* __restrict__ Wp,
    const float* __restrict__ bp)
{
    __shared__ float Ws[64 * 64];
    __shared__ float Fs[4][64];
    for (int i = threadIdx.x; i < 64 * 64; i += 256) Ws[i] = Wp[i];
    int r0 = blockIdx.x * 4;
    int rr = threadIdx.x >> 6;   // 0..3
    int c  = threadIdx.x & 63;
    Fs[rr][c] = feat[(r0 + rr) * 64 + c];
    __syncthreads();
    float acc = bp[c];
#pragma unroll
    for (int d = 0; d < 64; d++)
        acc = fmaf(Fs[rr][d], Ws[d * 64 + c], acc);
    g_f[(r0 + rr) * 64 + c] = acc;
}

// ---------------------------------------------------------------------------
// Kernel 2: brute-force KNN (top-16 smallest d2) + weight output
// thread-per-query; xyz1 staged in smem as float4(x,y,z,|p|^2)
// ---------------------------------------------------------------------------
#define KTILE 1024
__global__ __launch_bounds__(128) void knn_kernel(
    const float* __restrict__ xyz1, const float* __restrict__ xyz2,
    float* __restrict__ outW)
{
    __shared__ float4 tile[KTILE];
    int b = blockIdx.y;
    int m = blockIdx.x * 128 + threadIdx.x;
    const float* x2 = xyz2 + ((size_t)b * M + m) * 3;
    float qx = x2[0], qy = x2[1], qz = x2[2];
    float qs = qx * qx + qy * qy + qz * qz;

    float bd[KNN];
    int   bi[KNN];
#pragma unroll
    for (int j = 0; j < KNN; j++) { bd[j] = 3.4e38f; bi[j] = 0; }

    const float* base = xyz1 + (size_t)b * N * 3;
    for (int n0 = 0; n0 < N; n0 += KTILE) {
        for (int i = threadIdx.x; i < KTILE; i += 128) {
            float x = base[(n0 + i) * 3 + 0];
            float y = base[(n0 + i) * 3 + 1];
            float z = base[(n0 + i) * 3 + 2];
            tile[i] = make_float4(x, y, z, x * x + y * y + z * z);
        }
        __syncthreads();
#pragma unroll 8
        for (int jj = 0; jj < KTILE; jj++) {
            float4 p = tile[jj];
            float t = qx * p.x;
            t = fmaf(qy, p.y, t);
            t = fmaf(qz, p.z, t);
            float d = (qs + p.w) - 2.0f * t;   // same expanded formula as reference
            if (d < bd[KNN - 1]) {
                bd[KNN - 1] = d; bi[KNN - 1] = n0 + jj;
#pragma unroll
                for (int j = KNN - 1; j > 0; --j) {
                    if (bd[j] < bd[j - 1]) {
                        float td = bd[j]; bd[j] = bd[j - 1]; bd[j - 1] = td;
                        int   ti = bi[j]; bi[j] = bi[j - 1]; bi[j - 1] = ti;
                    }
                }
            }
        }
        __syncthreads();
    }
    size_t q = (size_t)b * M + m;
#pragma unroll
    for (int j = 0; j < KNN; j++) g_idx[q * KNN + j] = bi[j];
    outW[q] = (bd[0] > 0.03f) ? 10.0f : 1.0f;
}

// ---------------------------------------------------------------------------
// Kernel 3: gather + tiny MLP + weighted reduction
// warp-per-query; W2 columns register-resident (2 adjacent channels/lane),
// h staged in per-warp smem, read back via broadcast LDS.128
// ---------------------------------------------------------------------------
#define MLP_BLOCKS 256
__global__ __launch_bounds__(256) void mlp_kernel(
    const float* __restrict__ xyz1, const float* __restrict__ xyz2,
    const float* __restrict__ W1, const float* __restrict__ b1,
    const float* __restrict__ W2, const float* __restrict__ b2,
    float* __restrict__ out)
{
    __shared__ float Hs[8][KNN * 64];   // 32KB: per-warp h staging
    int lane = threadIdx.x & 31;
    int wid  = threadIdx.x >> 5;
    int c0   = lane * 2;

    // W2 columns c0, c0+1 in registers (reused across all queries this warp runs)
    float w2a[64], w2b[64];
#pragma unroll
    for (int d = 0; d < 64; d++) {
        w2a[d] = W2[d * 64 + c0];
        w2b[d] = W2[d * 64 + c0 + 1];
    }
    float w10a = W1[c0],        w10b = W1[c0 + 1];
    float w11a = W1[64 + c0],   w11b = W1[64 + c0 + 1];
    float w12a = W1[128 + c0],  w12b = W1[128 + c0 + 1];
    float b1a = b1[c0], b1b = b1[c0 + 1];
    float b2a = b2[c0], b2b = b2[c0 + 1];

    float* H = Hs[wid];
    int gw = blockIdx.x * 8 + wid;
    int nw = gridDim.x * 8;

    for (int q = gw; q < QTOT; q += nw) {
        int b = q >> 13;          // /8192
        int j16 = (lane < KNN) ? g_idx[q * KNN + lane] : 0;
        const float* x2 = xyz2 + (size_t)q * 3;
        float qx = x2[0], qy = x2[1], qz = x2[2];

        // phase 1: h[k][c] = relu(g_xyz @ W1 + b1)
#pragma unroll 4
        for (int k = 0; k < KNN; k++) {
            int j = __shfl_sync(0xffffffffu, j16, k);
            const float* p = xyz1 + ((size_t)b * N + j) * 3;
            float gx = p[0] - qx, gy = p[1] - qy, gz = p[2] - qz;
            float h0 = fmaf(gz, w12a, fmaf(gy, w11a, fmaf(gx, w10a, b1a)));
            float h1 = fmaf(gz, w12b, fmaf(gy, w11b, fmaf(gx, w10b, b1b)));
            H[k * 64 + c0]     = fmaxf(h0, 0.0f);
            H[k * 64 + c0 + 1] = fmaxf(h1, 0.0f);
        }
        __syncwarp();

        // phase 2: pw = h @ W2 + b2;  acc[c] += pw[c] * g_feature[c]
        float acc0 = 0.0f, acc1 = 0.0f;
#pragma unroll 1
        for (int k = 0; k < KNN; k++) {
            int j = __shfl_sync(0xffffffffu, j16, k);
            const float* fr = g_f + ((size_t)b * N + j) * 64;
            float gf0 = fr[c0], gf1 = fr[c0 + 1];
            float pw0x = b2a, pw0y = 0.0f, pw1x = b2b, pw1y = 0.0f;  // split accumulators for ILP
            const float4* h4 = (const float4*)(H + k * 64);
#pragma unroll
            for (int d4 = 0; d4 < 16; d4++) {
                float4 h = h4[d4];
                pw0x = fmaf(h.x, w2a[4 * d4 + 0], pw0x);
                pw1x = fmaf(h.x, w2b[4 * d4 + 0], pw1x);
                pw0y = fmaf(h.y, w2a[4 * d4 + 1], pw0y);
                pw1y = fmaf(h.y, w2b[4 * d4 + 1], pw1y);
                pw0x = fmaf(h.z, w2a[4 * d4 + 2], pw0x);
                pw1x = fmaf(h.z, w2b[4 * d4 + 2], pw1x);
                pw0y = fmaf(h.w, w2a[4 * d4 + 3], pw0y);
                pw1y = fmaf(h.w, w2b[4 * d4 + 3], pw1y);
            }
            acc0 = fmaf(pw0x + pw0y, gf0, acc0);
            acc1 = fmaf(pw1x + pw1y, gf1, acc1);
        }
        out[(size_t)q * 64 + c0]     = acc0 * 0.25f;   // 1/sqrt(16)
        out[(size_t)q * 64 + c0 + 1] = acc1 * 0.25f;
        __syncwarp();   // H reads done before next iter overwrites
    }
}

// ---------------------------------------------------------------------------
// launch
// ---------------------------------------------------------------------------
extern "C" void kernel_launch(void* const* d_in, const int* in_sizes, int n_in,
                              void* d_out, int out_size)
{
    const float* feature1 = (const float*)d_in[0];
    const float* xyz1     = (const float*)d_in[1];
    const float* xyz2     = (const float*)d_in[2];
    const float* Wp       = (const float*)d_in[3];
    const float* bp       = (const float*)d_in[4];
    const float* W1       = (const float*)d_in[5];
    const float* b1       = (const float*)d_in[6];
    const float* W2       = (const float*)d_in[7];
    const float* b2       = (const float*)d_in[8];

    float* out_feat = (float*)d_out;                       // [B*M*64]
    float* out_w    = (float*)d_out + (size_t)B * M * 64;  // [B*M]

    proj_kernel<<<(B * N) / 4, 256>>>(feature1, Wp, bp);
    dim3 kg(M / 128, B);
    knn_kernel<<<kg, 128>>>(xyz1, xyz2, out_w);
    mlp_kernel<<<MLP_BLOCKS, 256>>>(xyz1, xyz2, W1, b1, W2, b2, out_feat);
}

// round 9
// speedup vs baseline: 1.1795x; 1.1795x over previous
#include <cuda_runtime.h>
#include <cuda_bf16.h>

#define B 2
#define N 8192
#define M 8192
#define D 64
#define KNN 16
#define QTOT (B * M)

#define NCHUNK 4
#define CHUNK (N / NCHUNK)     // 2048
#define KTILE 1024

// Scratch (allocation-free: __device__ globals)
__device__ float g_f[B * N * D];                    // projected features, 4MB
__device__ int   g_idx[B * M * KNN];                // final knn indices
__device__ float g_pd[B * M * NCHUNK * KNN];        // partial top-16 dists, 8MB
__device__ int   g_pi[B * M * NCHUNK * KNN];        // partial top-16 ids,   8MB

// ---------------------------------------------------------------------------
// Kernel 1: f = feature1 @ Wp + bp    [B*N, 64] x [64, 64]
// ---------------------------------------------------------------------------
__global__ __launch_bounds__(256) void proj_kernel(
    const float* __restrict__ feat, const float* __restrict__ Wp,
    const float* __restrict__ bp)
{
    __shared__ float Ws[64 * 64];
    __shared__ float Fs[4][64];
    for (int i = threadIdx.x; i < 64 * 64; i += 256) Ws[i] = Wp[i];
    int r0 = blockIdx.x * 4;
    int rr = threadIdx.x >> 6;
    int c  = threadIdx.x & 63;
    Fs[rr][c] = feat[(r0 + rr) * 64 + c];
    __syncthreads();
    float acc = bp[c];
#pragma unroll
    for (int d = 0; d < 64; d++)
        acc = fmaf(Fs[rr][d], Ws[d * 64 + c], acc);
    g_f[(r0 + rr) * 64 + c] = acc;
}

// ---------------------------------------------------------------------------
// Kernel 2a: brute-force KNN over one N-chunk. Identical formula + insert
// logic to the round-3 passing kernel; only the scan range is split so we
// get 4x the warps (2048 total -> ~3.5/SMSP instead of 0.86).
// grid = (M/128, NCHUNK, B), block = 128
// ---------------------------------------------------------------------------
__global__ __launch_bounds__(128) void knn_part_kernel(
    const float* __restrict__ xyz1, const float* __restrict__ xyz2)
{
    __shared__ float4 tile[KTILE];
    int b     = blockIdx.z;
    int chunk = blockIdx.y;
    int m     = blockIdx.x * 128 + threadIdx.x;
    const float* x2 = xyz2 + ((size_t)b * M + m) * 3;
    float qx = x2[0], qy = x2[1], qz = x2[2];
    float qs = qx * qx + qy * qy + qz * qz;

    float bd[KNN];
    int   bi[KNN];
#pragma unroll
    for (int j = 0; j < KNN; j++) { bd[j] = 3.4e38f; bi[j] = 0; }

    const float* base = xyz1 + (size_t)b * N * 3;
    int nbeg = chunk * CHUNK;
    for (int n0 = nbeg; n0 < nbeg + CHUNK; n0 += KTILE) {
        for (int i = threadIdx.x; i < KTILE; i += 128) {
            float x = base[(n0 + i) * 3 + 0];
            float y = base[(n0 + i) * 3 + 1];
            float z = base[(n0 + i) * 3 + 2];
            tile[i] = make_float4(x, y, z, x * x + y * y + z * z);
        }
        __syncthreads();
#pragma unroll 8
        for (int jj = 0; jj < KTILE; jj++) {
            float4 p = tile[jj];
            float t = qx * p.x;
            t = fmaf(qy, p.y, t);
            t = fmaf(qz, p.z, t);
            float d = (qs + p.w) - 2.0f * t;   // bitwise-same formula as round 3
            if (d < bd[KNN - 1]) {
                bd[KNN - 1] = d; bi[KNN - 1] = n0 + jj;
#pragma unroll
                for (int j = KNN - 1; j > 0; --j) {
                    if (bd[j] < bd[j - 1]) {
                        float td = bd[j]; bd[j] = bd[j - 1]; bd[j - 1] = td;
                        int   ti = bi[j]; bi[j] = bi[j - 1]; bi[j - 1] = ti;
                    }
                }
            }
        }
        __syncthreads();
    }
    size_t q = (size_t)b * M + m;
    float* pd = g_pd + (q * NCHUNK + chunk) * KNN;
    int*   pi = g_pi + (q * NCHUNK + chunk) * KNN;
#pragma unroll
    for (int j = 0; j < KNN; j++) { pd[j] = bd[j]; pi[j] = bi[j]; }
}

// ---------------------------------------------------------------------------
// Kernel 2b: exact 4-way merge of sorted partial lists -> global top-16.
// Ties prefer the earliest chunk (== ascending-n order, matching a single
// ascending scan with strict-< insertion).
// ---------------------------------------------------------------------------
__global__ __launch_bounds__(256) void knn_merge_kernel(float* __restrict__ outW)
{
    int q = blockIdx.x * 256 + threadIdx.x;
    if (q >= QTOT) return;
    const float* pd = g_pd + (size_t)q * NCHUNK * KNN;
    const int*   pi = g_pi + (size_t)q * NCHUNK * KNN;

    int   ptr[NCHUNK];
    float head[NCHUNK];
#pragma unroll
    for (int c = 0; c < NCHUNK; c++) { ptr[c] = 0; head[c] = pd[c * KNN]; }

    float first = 3.4e38f;
#pragma unroll
    for (int j = 0; j < KNN; j++) {
        int best = 0; float bv = head[0];
#pragma unroll
        for (int c = 1; c < NCHUNK; c++)
            if (head[c] < bv) { bv = head[c]; best = c; }   // strict: earliest chunk wins ties
        g_idx[(size_t)q * KNN + j] = pi[best * KNN + ptr[best]];
        if (j == 0) first = bv;
        ptr[best]++;
        head[best] = (ptr[best] < KNN) ? pd[best * KNN + ptr[best]] : 3.4e38f;
    }
    outW[q] = (first > 0.03f) ? 10.0f : 1.0f;
}

// ---------------------------------------------------------------------------
// Kernel 3: gather + tiny MLP + weighted reduction (unchanged, known-good)
// ---------------------------------------------------------------------------
#define MLP_BLOCKS 256
__global__ __launch_bounds__(256) void mlp_kernel(
    const float* __restrict__ xyz1, const float* __restrict__ xyz2,
    const float* __restrict__ W1, const float* __restrict__ b1,
    const float* __restrict__ W2, const float* __restrict__ b2,
    float* __restrict__ out)
{
    __shared__ float Hs[8][KNN * 64];
    int lane = threadIdx.x & 31;
    int wid  = threadIdx.x >> 5;
    int c0   = lane * 2;

    float w2a[64], w2b[64];
#pragma unroll
    for (int d = 0; d < 64; d++) {
        w2a[d] = W2[d * 64 + c0];
        w2b[d] = W2[d * 64 + c0 + 1];
    }
    float w10a = W1[c0],        w10b = W1[c0 + 1];
    float w11a = W1[64 + c0],   w11b = W1[64 + c0 + 1];
    float w12a = W1[128 + c0],  w12b = W1[128 + c0 + 1];
    float b1a = b1[c0], b1b = b1[c0 + 1];
    float b2a = b2[c0], b2b = b2[c0 + 1];

    float* H = Hs[wid];
    int gw = blockIdx.x * 8 + wid;
    int nw = gridDim.x * 8;

    for (int q = gw; q < QTOT; q += nw) {
        int b = q >> 13;
        int j16 = (lane < KNN) ? g_idx[(size_t)q * KNN + lane] : 0;
        const float* x2 = xyz2 + (size_t)q * 3;
        float qx = x2[0], qy = x2[1], qz = x2[2];

#pragma unroll 4
        for (int k = 0; k < KNN; k++) {
            int j = __shfl_sync(0xffffffffu, j16, k);
            const float* p = xyz1 + ((size_t)b * N + j) * 3;
            float gx = p[0] - qx, gy = p[1] - qy, gz = p[2] - qz;
            float h0 = fmaf(gz, w12a, fmaf(gy, w11a, fmaf(gx, w10a, b1a)));
            float h1 = fmaf(gz, w12b, fmaf(gy, w11b, fmaf(gx, w10b, b1b)));
            H[k * 64 + c0]     = fmaxf(h0, 0.0f);
            H[k * 64 + c0 + 1] = fmaxf(h1, 0.0f);
        }
        __syncwarp();

        float acc0 = 0.0f, acc1 = 0.0f;
#pragma unroll 1
        for (int k = 0; k < KNN; k++) {
            int j = __shfl_sync(0xffffffffu, j16, k);
            const float* fr = g_f + ((size_t)b * N + j) * 64;
            float gf0 = fr[c0], gf1 = fr[c0 + 1];
            float pw0x = b2a, pw0y = 0.0f, pw1x = b2b, pw1y = 0.0f;
            const float4* h4 = (const float4*)(H + k * 64);
#pragma unroll
            for (int d4 = 0; d4 < 16; d4++) {
                float4 h = h4[d4];
                pw0x = fmaf(h.x, w2a[4 * d4 + 0], pw0x);
                pw1x = fmaf(h.x, w2b[4 * d4 + 0], pw1x);
                pw0y = fmaf(h.y, w2a[4 * d4 + 1], pw0y);
                pw1y = fmaf(h.y, w2b[4 * d4 + 1], pw1y);
                pw0x = fmaf(h.z, w2a[4 * d4 + 2], pw0x);
                pw1x = fmaf(h.z, w2b[4 * d4 + 2], pw1x);
                pw0y = fmaf(h.w, w2a[4 * d4 + 3], pw0y);
                pw1y = fmaf(h.w, w2b[4 * d4 + 3], pw1y);
            }
            acc0 = fmaf(pw0x + pw0y, gf0, acc0);
            acc1 = fmaf(pw1x + pw1y, gf1, acc1);
        }
        out[(size_t)q * 64 + c0]     = acc0 * 0.25f;
        out[(size_t)q * 64 + c0 + 1] = acc1 * 0.25f;
        __syncwarp();
    }
}

// ---------------------------------------------------------------------------
// launch
// ---------------------------------------------------------------------------
extern "C" void kernel_launch(void* const* d_in, const int* in_sizes, int n_in,
                              void* d_out, int out_size)
{
    const float* feature1 = (const float*)d_in[0];
    const float* xyz1     = (const float*)d_in[1];
    const float* xyz2     = (const float*)d_in[2];
    const float* Wp       = (const float*)d_in[3];
    const float* bp       = (const float*)d_in[4];
    const float* W1       = (const float*)d_in[5];
    const float* b1       = (const float*)d_in[6];
    const float* W2       = (const float*)d_in[7];
    const float* b2       = (const float*)d_in[8];

    float* out_feat = (float*)d_out;                       // [B*M*64]
    float* out_w    = (float*)d_out + (size_t)B * M * 64;  // [B*M]

    proj_kernel<<<(B * N) / 4, 256>>>(feature1, Wp, bp);

    dim3 kg(M / 128, NCHUNK, B);
    knn_part_kernel<<<kg, 128>>>(xyz1, xyz2);
    knn_merge_kernel<<<(QTOT + 255) / 256, 256>>>(out_w);

    mlp_kernel<<<MLP_BLOCKS, 256>>>(xyz1, xyz2, W1, b1, W2, b2, out_feat);
}

// round 10
// speedup vs baseline: 1.7366x; 1.4724x over previous
#include <cuda_runtime.h>
#include <cuda_bf16.h>

#define B 2
#define N 8192
#define M 8192
#define D 64
#define KNN 16
#define QTOT (B * M)

#define NCHUNK 4
#define CHUNK (N / NCHUNK)     // 2048
#define KTILE 1024
#define SENT 3.4e38f

// Scratch (allocation-free: __device__ globals)
__device__ float g_f[B * N * D];                    // projected features, 4MB
__device__ int   g_idx[B * M * KNN];                // final knn indices
__device__ float g_pd[B * M * NCHUNK * KNN];        // partial top-16 dists, 8MB
__device__ int   g_pi[B * M * NCHUNK * KNN];        // partial top-16 ids,   8MB

// Per-query radius^2 threshold covering ~TARGET points in expectation.
// Axis-clip factor handles boundary queries (exact for half-space cuts).
// Only a performance hint: merge kernel verifies completeness and falls
// back to a full scan when fewer than KNN candidates pass.
__device__ __forceinline__ float query_thresh(float qx, float qy, float qz) {
    const float TARGET = 48.0f;
    const float KVOL = (float)N * 4.18879f;   // N * (4/3)pi
    float r = cbrtf(TARGET / KVOL);
#pragma unroll
    for (int it = 0; it < 3; it++) {
        float inv2r = 0.5f / r;
        float fx = (fminf(qx, r) + fminf(1.0f - qx, r)) * inv2r;
        float fy = (fminf(qy, r) + fminf(1.0f - qy, r)) * inv2r;
        float fz = (fminf(qz, r) + fminf(1.0f - qz, r)) * inv2r;
        float c = fmaxf(fx * fy * fz, 0.125f);
        r = cbrtf(TARGET / (KVOL * c));
    }
    return r * r;
}

// ---------------------------------------------------------------------------
// Kernel 1: f = feature1 @ Wp + bp
// ---------------------------------------------------------------------------
__global__ __launch_bounds__(256) void proj_kernel(
    const float* __restrict__ feat, const float* __restrict__ Wp,
    const float* __restrict__ bp)
{
    __shared__ float Ws[64 * 64];
    __shared__ float Fs[4][64];
    for (int i = threadIdx.x; i < 64 * 64; i += 256) Ws[i] = Wp[i];
    int r0 = blockIdx.x * 4;
    int rr = threadIdx.x >> 6;
    int c  = threadIdx.x & 63;
    Fs[rr][c] = feat[(r0 + rr) * 64 + c];
    __syncthreads();
    float acc = bp[c];
#pragma unroll
    for (int d = 0; d < 64; d++)
        acc = fmaf(Fs[rr][d], Ws[d * 64 + c], acc);
    g_f[(r0 + rr) * 64 + c] = acc;
}

// ---------------------------------------------------------------------------
// Kernel 2a: threshold-filtered brute-force KNN over one N-chunk.
// Same formula + insert ordering as the passing kernel; the T filter only
// suppresses inserts that provably can't reach the global top-16 (verified
// later). grid = (M/128, NCHUNK, B), block = 128
// ---------------------------------------------------------------------------
__global__ __launch_bounds__(128) void knn_part_kernel(
    const float* __restrict__ xyz1, const float* __restrict__ xyz2)
{
    __shared__ float4 tile[KTILE];
    int b     = blockIdx.z;
    int chunk = blockIdx.y;
    int m     = blockIdx.x * 128 + threadIdx.x;
    const float* x2 = xyz2 + ((size_t)b * M + m) * 3;
    float qx = x2[0], qy = x2[1], qz = x2[2];
    float qs = qx * qx + qy * qy + qz * qz;
    float T  = query_thresh(qx, qy, qz);

    float bd[KNN];
    int   bi[KNN];
#pragma unroll
    for (int j = 0; j < KNN; j++) { bd[j] = SENT; bi[j] = 0; }

    const float* base = xyz1 + (size_t)b * N * 3;
    int nbeg = chunk * CHUNK;
    for (int n0 = nbeg; n0 < nbeg + CHUNK; n0 += KTILE) {
        for (int i = threadIdx.x; i < KTILE; i += 128) {
            float x = base[(n0 + i) * 3 + 0];
            float y = base[(n0 + i) * 3 + 1];
            float z = base[(n0 + i) * 3 + 2];
            tile[i] = make_float4(x, y, z, x * x + y * y + z * z);
        }
        __syncthreads();
#pragma unroll 8
        for (int jj = 0; jj < KTILE; jj++) {
            float4 p = tile[jj];
            float t = qx * p.x;
            t = fmaf(qy, p.y, t);
            t = fmaf(qz, p.z, t);
            float d = (qs + p.w) - 2.0f * t;   // bitwise-same formula as before
            if (d < fminf(T, bd[KNN - 1])) {
                bd[KNN - 1] = d; bi[KNN - 1] = n0 + jj;
#pragma unroll
                for (int j = KNN - 1; j > 0; --j) {
                    if (bd[j] < bd[j - 1]) {
                        float td = bd[j]; bd[j] = bd[j - 1]; bd[j - 1] = td;
                        int   ti = bi[j]; bi[j] = bi[j - 1]; bi[j - 1] = ti;
                    }
                }
            }
        }
        __syncthreads();
    }
    size_t q = (size_t)b * M + m;
    float* pd = g_pd + (q * NCHUNK + chunk) * KNN;
    int*   pi = g_pi + (q * NCHUNK + chunk) * KNN;
#pragma unroll
    for (int j = 0; j < KNN; j++) { pd[j] = bd[j]; pi[j] = bi[j]; }
}

// ---------------------------------------------------------------------------
// Kernel 2b: exact 4-way merge. If fewer than KNN candidates passed the
// filter (16th merged value is the sentinel), redo this query with a full
// unfiltered scan — guarantees exactness independent of T.
// ---------------------------------------------------------------------------
__global__ __launch_bounds__(256) void knn_merge_kernel(
    const float* __restrict__ xyz1, const float* __restrict__ xyz2,
    float* __restrict__ outW)
{
    int q = blockIdx.x * 256 + threadIdx.x;
    if (q >= QTOT) return;
    const float* pd = g_pd + (size_t)q * NCHUNK * KNN;
    const int*   pi = g_pi + (size_t)q * NCHUNK * KNN;

    int   ptr[NCHUNK];
    float head[NCHUNK];
#pragma unroll
    for (int c = 0; c < NCHUNK; c++) { ptr[c] = 0; head[c] = pd[c * KNN]; }

    int   outi[KNN];
    float first = SENT, last = SENT;
#pragma unroll
    for (int j = 0; j < KNN; j++) {
        int best = 0; float bv = head[0];
#pragma unroll
        for (int c = 1; c < NCHUNK; c++)
            if (head[c] < bv) { bv = head[c]; best = c; }   // earliest chunk wins ties
        outi[j] = pi[best * KNN + ptr[best]];
        if (j == 0) first = bv;
        last = bv;
        ptr[best]++;
        head[best] = (ptr[best] < KNN) ? pd[best * KNN + ptr[best]] : SENT;
    }

    if (last >= SENT) {
        // fallback: full unfiltered scan (exactness guarantee; ~never taken)
        int b = q >> 13;
        const float* x2 = xyz2 + (size_t)q * 3;
        float qx = x2[0], qy = x2[1], qz = x2[2];
        float qs = qx * qx + qy * qy + qz * qz;
        float bd[KNN];
#pragma unroll
        for (int j = 0; j < KNN; j++) { bd[j] = SENT; outi[j] = 0; }
        const float* base = xyz1 + (size_t)b * N * 3;
        for (int n = 0; n < N; n++) {
            float x = base[n * 3], y = base[n * 3 + 1], z = base[n * 3 + 2];
            float ps = x * x + y * y + z * z;
            float t = qx * x;
            t = fmaf(qy, y, t);
            t = fmaf(qz, z, t);
            float d = (qs + ps) - 2.0f * t;
            if (d < bd[KNN - 1]) {
                bd[KNN - 1] = d; outi[KNN - 1] = n;
#pragma unroll
                for (int j = KNN - 1; j > 0; --j) {
                    if (bd[j] < bd[j - 1]) {
                        float td = bd[j]; bd[j] = bd[j - 1]; bd[j - 1] = td;
                        int   ti = outi[j]; outi[j] = outi[j - 1]; outi[j - 1] = ti;
                    }
                }
            }
        }
        first = bd[0];
    }

#pragma unroll
    for (int j = 0; j < KNN; j++) g_idx[(size_t)q * KNN + j] = outi[j];
    outW[q] = (first > 0.03f) ? 10.0f : 1.0f;
}

// ---------------------------------------------------------------------------
// Kernel 3: gather + tiny MLP + weighted reduction.
// Unchanged math; grid raised 256 -> 2048 (was 1.7 blocks/SM, occ 12%).
// ---------------------------------------------------------------------------
#define MLP_BLOCKS 2048
__global__ __launch_bounds__(256) void mlp_kernel(
    const float* __restrict__ xyz1, const float* __restrict__ xyz2,
    const float* __restrict__ W1, const float* __restrict__ b1,
    const float* __restrict__ W2, const float* __restrict__ b2,
    float* __restrict__ out)
{
    __shared__ float Hs[8][KNN * 64];
    int lane = threadIdx.x & 31;
    int wid  = threadIdx.x >> 5;
    int c0   = lane * 2;

    float w2a[64], w2b[64];
#pragma unroll
    for (int d = 0; d < 64; d++) {
        w2a[d] = W2[d * 64 + c0];
        w2b[d] = W2[d * 64 + c0 + 1];
    }
    float w10a = W1[c0],        w10b = W1[c0 + 1];
    float w11a = W1[64 + c0],   w11b = W1[64 + c0 + 1];
    float w12a = W1[128 + c0],  w12b = W1[128 + c0 + 1];
    float b1a = b1[c0], b1b = b1[c0 + 1];
    float b2a = b2[c0], b2b = b2[c0 + 1];

    float* H = Hs[wid];
    int gw = blockIdx.x * 8 + wid;
    int nw = MLP_BLOCKS * 8;

    for (int q = gw; q < QTOT; q += nw) {
        int b = q >> 13;
        int j16 = (lane < KNN) ? g_idx[(size_t)q * KNN + lane] : 0;
        const float* x2 = xyz2 + (size_t)q * 3;
        float qx = x2[0], qy = x2[1], qz = x2[2];

#pragma unroll 4
        for (int k = 0; k < KNN; k++) {
            int j = __shfl_sync(0xffffffffu, j16, k);
            const float* p = xyz1 + ((size_t)b * N + j) * 3;
            float gx = p[0] - qx, gy = p[1] - qy, gz = p[2] - qz;
            float h0 = fmaf(gz, w12a, fmaf(gy, w11a, fmaf(gx, w10a, b1a)));
            float h1 = fmaf(gz, w12b, fmaf(gy, w11b, fmaf(gx, w10b, b1b)));
            H[k * 64 + c0]     = fmaxf(h0, 0.0f);
            H[k * 64 + c0 + 1] = fmaxf(h1, 0.0f);
        }
        __syncwarp();

        float acc0 = 0.0f, acc1 = 0.0f;
#pragma unroll 1
        for (int k = 0; k < KNN; k++) {
            int j = __shfl_sync(0xffffffffu, j16, k);
            const float* fr = g_f + ((size_t)b * N + j) * 64;
            float gf0 = fr[c0], gf1 = fr[c0 + 1];
            float pw0x = b2a, pw0y = 0.0f, pw1x = b2b, pw1y = 0.0f;
            const float4* h4 = (const float4*)(H + k * 64);
#pragma unroll
            for (int d4 = 0; d4 < 16; d4++) {
                float4 h = h4[d4];
                pw0x = fmaf(h.x, w2a[4 * d4 + 0], pw0x);
                pw1x = fmaf(h.x, w2b[4 * d4 + 0], pw1x);
                pw0y = fmaf(h.y, w2a[4 * d4 + 1], pw0y);
                pw1y = fmaf(h.y, w2b[4 * d4 + 1], pw1y);
                pw0x = fmaf(h.z, w2a[4 * d4 + 2], pw0x);
                pw1x = fmaf(h.z, w2b[4 * d4 + 2], pw1x);
                pw0y = fmaf(h.w, w2a[4 * d4 + 3], pw0y);
                pw1y = fmaf(h.w, w2b[4 * d4 + 3], pw1y);
            }
            acc0 = fmaf(pw0x + pw0y, gf0, acc0);
            acc1 = fmaf(pw1x + pw1y, gf1, acc1);
        }
        out[(size_t)q * 64 + c0]     = acc0 * 0.25f;
        out[(size_t)q * 64 + c0 + 1] = acc1 * 0.25f;
        __syncwarp();
    }
}

// ---------------------------------------------------------------------------
// launch
// ---------------------------------------------------------------------------
extern "C" void kernel_launch(void* const* d_in, const int* in_sizes, int n_in,
                              void* d_out, int out_size)
{
    const float* feature1 = (const float*)d_in[0];
    const float* xyz1     = (const float*)d_in[1];
    const float* xyz2     = (const float*)d_in[2];
    const float* Wp       = (const float*)d_in[3];
    const float* bp       = (const float*)d_in[4];
    const float* W1       = (const float*)d_in[5];
    const float* b1       = (const float*)d_in[6];
    const float* W2       = (const float*)d_in[7];
    const float* b2       = (const float*)d_in[8];

    float* out_feat = (float*)d_out;                       // [B*M*64]
    float* out_w    = (float*)d_out + (size_t)B * M * 64;  // [B*M]

    proj_kernel<<<(B * N) / 4, 256>>>(feature1, Wp, bp);

    dim3 kg(M / 128, NCHUNK, B);
    knn_part_kernel<<<kg, 128>>>(xyz1, xyz2);
    knn_merge_kernel<<<(QTOT + 255) / 256, 256>>>(xyz1, xyz2, out_w);

    mlp_kernel<<<MLP_BLOCKS, 256>>>(xyz1, xyz2, W1, b1, W2, b2, out_feat);
}

// round 11
// speedup vs baseline: 2.1381x; 1.2312x over previous
#include <cuda_runtime.h>
#include <cuda_bf16.h>

#define B 2
#define N 8192
#define M 8192
#define D 64
#define KNN 16
#define QTOT (B * M)

#define NCHUNK 8
#define CHUNK (N / NCHUNK)     // 1024
#define SENT 3.4e38f

// Scratch (allocation-free: __device__ globals)
__device__ float g_f[B * N * D];                    // projected features, 4MB
__device__ int   g_idx[B * M * KNN];                // final knn indices
__device__ float g_pd[B * M * NCHUNK * KNN];        // partial top-16 dists, 8MB
__device__ int   g_pi[B * M * NCHUNK * KNN];        // partial top-16 ids,   8MB

// Per-query radius^2 threshold covering ~TARGET points in expectation.
// Performance hint only: merge kernel verifies completeness and falls back.
__device__ __forceinline__ float query_thresh(float qx, float qy, float qz) {
    const float TARGET = 48.0f;
    const float KVOL = (float)N * 4.18879f;   // N * (4/3)pi
    float r = cbrtf(TARGET / KVOL);
#pragma unroll
    for (int it = 0; it < 3; it++) {
        float inv2r = 0.5f / r;
        float fx = (fminf(qx, r) + fminf(1.0f - qx, r)) * inv2r;
        float fy = (fminf(qy, r) + fminf(1.0f - qy, r)) * inv2r;
        float fz = (fminf(qz, r) + fminf(1.0f - qz, r)) * inv2r;
        float c = fmaxf(fx * fy * fz, 0.125f);
        r = cbrtf(TARGET / (KVOL * c));
    }
    return r * r;
}

// ---------------------------------------------------------------------------
// Kernel 1: f = feature1 @ Wp + bp
// ---------------------------------------------------------------------------
__global__ __launch_bounds__(256) void proj_kernel(
    const float* __restrict__ feat, const float* __restrict__ Wp,
    const float* __restrict__ bp)
{
    __shared__ float Ws[64 * 64];
    __shared__ float Fs[4][64];
    for (int i = threadIdx.x; i < 64 * 64; i += 256) Ws[i] = Wp[i];
    int r0 = blockIdx.x * 4;
    int rr = threadIdx.x >> 6;
    int c  = threadIdx.x & 63;
    Fs[rr][c] = feat[(r0 + rr) * 64 + c];
    __syncthreads();
    float acc = bp[c];
#pragma unroll
    for (int d = 0; d < 64; d++)
        acc = fmaf(Fs[rr][d], Ws[d * 64 + c], acc);
    g_f[(r0 + rr) * 64 + c] = acc;
}

// ---------------------------------------------------------------------------
// Kernel 2a: threshold-filtered brute-force KNN over one 1024-point chunk.
// Same formula + strict-< insert ordering as the passing kernel.
// grid = (M/128, NCHUNK, B), block = 128
// ---------------------------------------------------------------------------
__global__ __launch_bounds__(128) void knn_part_kernel(
    const float* __restrict__ xyz1, const float* __restrict__ xyz2)
{
    __shared__ float4 tile[CHUNK];
    int b     = blockIdx.z;
    int chunk = blockIdx.y;
    int m     = blockIdx.x * 128 + threadIdx.x;
    const float* x2 = xyz2 + ((size_t)b * M + m) * 3;
    float qx = x2[0], qy = x2[1], qz = x2[2];
    float qs = qx * qx + qy * qy + qz * qz;
    float T  = query_thresh(qx, qy, qz);

    float bd[KNN];
    int   bi[KNN];
#pragma unroll
    for (int j = 0; j < KNN; j++) { bd[j] = SENT; bi[j] = 0; }

    int nbeg = chunk * CHUNK;
    const float* base = xyz1 + ((size_t)b * N + nbeg) * 3;
    for (int i = threadIdx.x; i < CHUNK; i += 128) {
        float x = base[i * 3 + 0];
        float y = base[i * 3 + 1];
        float z = base[i * 3 + 2];
        tile[i] = make_float4(x, y, z, x * x + y * y + z * z);
    }
    __syncthreads();

    float thr = T;   // == fminf(T, bd[15]) since bd[15]==SENT
#pragma unroll 8
    for (int jj = 0; jj < CHUNK; jj++) {
        float4 p = tile[jj];
        float t = qx * p.x;
        t = fmaf(qy, p.y, t);
        t = fmaf(qz, p.z, t);
        float d = (qs + p.w) - 2.0f * t;   // bitwise-same formula as before
        if (d < thr) {
            bd[KNN - 1] = d; bi[KNN - 1] = nbeg + jj;
#pragma unroll
            for (int j = KNN - 1; j > 0; --j) {
                if (bd[j] < bd[j - 1]) {
                    float td = bd[j]; bd[j] = bd[j - 1]; bd[j - 1] = td;
                    int   ti = bi[j]; bi[j] = bi[j - 1]; bi[j - 1] = ti;
                }
            }
            thr = fminf(T, bd[KNN - 1]);
        }
    }

    size_t q = (size_t)b * M + m;
    float* pd = g_pd + (q * NCHUNK + chunk) * KNN;
    int*   pi = g_pi + (q * NCHUNK + chunk) * KNN;
#pragma unroll
    for (int j = 0; j < KNN; j++) { pd[j] = bd[j]; pi[j] = bi[j]; }
}

// ---------------------------------------------------------------------------
// Kernel 2b: exact 8-way merge. Fallback to full scan if <16 passed filter.
// ---------------------------------------------------------------------------
__global__ __launch_bounds__(256) void knn_merge_kernel(
    const float* __restrict__ xyz1, const float* __restrict__ xyz2,
    float* __restrict__ outW)
{
    int q = blockIdx.x * 256 + threadIdx.x;
    if (q >= QTOT) return;
    const float* pd = g_pd + (size_t)q * NCHUNK * KNN;
    const int*   pi = g_pi + (size_t)q * NCHUNK * KNN;

    int   ptr[NCHUNK];
    float head[NCHUNK];
#pragma unroll
    for (int c = 0; c < NCHUNK; c++) { ptr[c] = 0; head[c] = pd[c * KNN]; }

    int   outi[KNN];
    float first = SENT, last = SENT;
#pragma unroll
    for (int j = 0; j < KNN; j++) {
        int best = 0; float bv = head[0];
#pragma unroll
        for (int c = 1; c < NCHUNK; c++)
            if (head[c] < bv) { bv = head[c]; best = c; }   // earliest chunk wins ties
        outi[j] = pi[best * KNN + ptr[best]];
        if (j == 0) first = bv;
        last = bv;
        ptr[best]++;
        head[best] = (ptr[best] < KNN) ? pd[best * KNN + ptr[best]] : SENT;
    }

    if (last >= SENT) {
        // fallback: full unfiltered scan (exactness guarantee; ~never taken)
        int b = q >> 13;
        const float* x2 = xyz2 + (size_t)q * 3;
        float qx = x2[0], qy = x2[1], qz = x2[2];
        float qs = qx * qx + qy * qy + qz * qz;
        float bd[KNN];
#pragma unroll
        for (int j = 0; j < KNN; j++) { bd[j] = SENT; outi[j] = 0; }
        const float* base = xyz1 + (size_t)b * N * 3;
        for (int n = 0; n < N; n++) {
            float x = base[n * 3], y = base[n * 3 + 1], z = base[n * 3 + 2];
            float ps = x * x + y * y + z * z;
            float t = qx * x;
            t = fmaf(qy, y, t);
            t = fmaf(qz, z, t);
            float d = (qs + ps) - 2.0f * t;
            if (d < bd[KNN - 1]) {
                bd[KNN - 1] = d; outi[KNN - 1] = n;
#pragma unroll
                for (int j = KNN - 1; j > 0; --j) {
                    if (bd[j] < bd[j - 1]) {
                        float td = bd[j]; bd[j] = bd[j - 1]; bd[j - 1] = td;
                        int   ti = outi[j]; outi[j] = outi[j - 1]; outi[j - 1] = ti;
                    }
                }
            }
        }
        first = bd[0];
    }

#pragma unroll
    for (int j = 0; j < KNN; j++) g_idx[(size_t)q * KNN + j] = outi[j];
    outW[q] = (first > 0.03f) ? 10.0f : 1.0f;
}

// ---------------------------------------------------------------------------
// Kernel 3: gather + tiny MLP + weighted reduction.
// RESTRUCTURED: 2 warps per query, 1 output channel per lane -> W2 column
// footprint 64 regs (was 128) -> ~100 regs -> 4 blocks/SM (16 warps, 25% occ
// vs RF-capped 12.5%). Math identical per channel; only accumulator split
// pattern differs (4-way).
// ---------------------------------------------------------------------------
#define MLP_BLOCKS 1024         // 2048 pairs -> exactly 8 queries each
__global__ __launch_bounds__(128, 4) void mlp_kernel(
    const float* __restrict__ xyz1, const float* __restrict__ xyz2,
    const float* __restrict__ W1, const float* __restrict__ b1,
    const float* __restrict__ W2, const float* __restrict__ b2,
    float* __restrict__ out)
{
    __shared__ float Hs[2][KNN * 64];   // 8KB: per-pair h staging
    int lane = threadIdx.x & 31;
    int wid  = threadIdx.x >> 5;
    int pair = wid >> 1;                // 0..1 within block
    int c    = ((wid & 1) << 5) + lane; // my output channel 0..63

    float w2c[64];
#pragma unroll
    for (int d = 0; d < 64; d++) w2c[d] = W2[d * 64 + c];
    float w10 = W1[c], w11 = W1[64 + c], w12 = W1[128 + c];
    float b1c = b1[c], b2c = b2[c];

    float* H = Hs[pair];
    int gp = blockIdx.x * 2 + pair;     // global pair id 0..2047

#pragma unroll 1
    for (int q = gp; q < QTOT; q += 2 * MLP_BLOCKS) {   // exactly 8 iters/pair
        int b = q >> 13;
        int j16 = (lane < KNN) ? g_idx[(size_t)q * KNN + lane] : 0;
        const float* x2 = xyz2 + (size_t)q * 3;
        float qx = x2[0], qy = x2[1], qz = x2[2];

        // phase 1: h[k][c] = relu(g_xyz @ W1 + b1), one channel per lane
#pragma unroll 4
        for (int k = 0; k < KNN; k++) {
            int j = __shfl_sync(0xffffffffu, j16, k);
            const float* p = xyz1 + ((size_t)b * N + j) * 3;
            float gx = p[0] - qx, gy = p[1] - qy, gz = p[2] - qz;
            float h = fmaf(gz, w12, fmaf(gy, w11, fmaf(gx, w10, b1c)));
            H[k * 64 + c] = fmaxf(h, 0.0f);
        }
        __syncthreads();   // both warps of the pair (uniform count block-wide)

        // phase 2: pw[c] = b2 + h . W2col ; acc += pw * g_feature[c]
        float acc = 0.0f;
#pragma unroll 1
        for (int k = 0; k < KNN; k++) {
            int j = __shfl_sync(0xffffffffu, j16, k);
            float gf = g_f[((size_t)b * N + j) * 64 + c];
            float p0 = b2c, p1 = 0.0f, p2 = 0.0f, p3 = 0.0f;
            const float4* h4 = (const float4*)(H + k * 64);
#pragma unroll
            for (int d4 = 0; d4 < 16; d4++) {
                float4 h = h4[d4];
                p0 = fmaf(h.x, w2c[4 * d4 + 0], p0);
                p1 = fmaf(h.y, w2c[4 * d4 + 1], p1);
                p2 = fmaf(h.z, w2c[4 * d4 + 2], p2);
                p3 = fmaf(h.w, w2c[4 * d4 + 3], p3);
            }
            acc = fmaf((p0 + p1) + (p2 + p3), gf, acc);
        }
        out[(size_t)q * 64 + c] = acc * 0.25f;   // 1/sqrt(16)
        __syncthreads();   // H reads done before next query overwrites
    }
}

// ---------------------------------------------------------------------------
// launch
// ---------------------------------------------------------------------------
extern "C" void kernel_launch(void* const* d_in, const int* in_sizes, int n_in,
                              void* d_out, int out_size)
{
    const float* feature1 = (const float*)d_in[0];
    const float* xyz1     = (const float*)d_in[1];
    const float* xyz2     = (const float*)d_in[2];
    const float* Wp       = (const float*)d_in[3];
    const float* bp       = (const float*)d_in[4];
    const float* W1       = (const float*)d_in[5];
    const float* b1       = (const float*)d_in[6];
    const float* W2       = (const float*)d_in[7];
    const float* b2       = (const float*)d_in[8];

    float* out_feat = (float*)d_out;                       // [B*M*64]
    float* out_w    = (float*)d_out + (size_t)B * M * 64;  // [B*M]

    proj_kernel<<<(B * N) / 4, 256>>>(feature1, Wp, bp);

    dim3 kg(M / 128, NCHUNK, B);
    knn_part_kernel<<<kg, 128>>>(xyz1, xyz2);
    knn_merge_kernel<<<(QTOT + 255) / 256, 256>>>(xyz1, xyz2, out_w);

    mlp_kernel<<<MLP_BLOCKS, 128>>>(xyz1, xyz2, W1, b1, W2, b2, out_feat);
}

// round 13
// speedup vs baseline: 2.9938x; 1.4002x over previous
#include <cuda_runtime.h>
#include <cuda_bf16.h>

#define B 2
#define N 8192
#define M 8192
#define D 64
#define KNN 16
#define QTOT (B * M)

#define NCHUNK 8
#define CHUNK (N / NCHUNK)     // 1024
#define CAP 24                 // per-thread append-stack capacity per chunk
#define SENT 3.4e38f

// Scratch (allocation-free: __device__ globals)
__device__ float g_f[B * N * D];                    // projected features, 4MB
__device__ int   g_idx[B * M * KNN];                // final knn indices
__device__ float g_pd[B * M * NCHUNK * KNN];        // partial top-16 dists
__device__ int   g_pi[B * M * NCHUNK * KNN];        // partial top-16 ids
__device__ int   g_ovf[B * M * NCHUNK];             // overflow flags

// Per-query radius^2 threshold covering ~TARGET points in expectation.
// Performance hint only: merge kernel verifies completeness and falls back.
__device__ __forceinline__ float query_thresh(float qx, float qy, float qz) {
    const float TARGET = 48.0f;
    const float KVOL = (float)N * 4.18879f;   // N * (4/3)pi
    float r = cbrtf(TARGET / KVOL);
#pragma unroll
    for (int it = 0; it < 3; it++) {
        float inv2r = 0.5f / r;
        float fx = (fminf(qx, r) + fminf(1.0f - qx, r)) * inv2r;
        float fy = (fminf(qy, r) + fminf(1.0f - qy, r)) * inv2r;
        float fz = (fminf(qz, r) + fminf(1.0f - qz, r)) * inv2r;
        float c = fmaxf(fx * fy * fz, 0.125f);
        r = cbrtf(TARGET / (KVOL * c));
    }
    return r * r;
}

// ---------------------------------------------------------------------------
// Kernel 1: f = feature1 @ Wp + bp. 16 rows/block to amortize the Ws fill;
// per-row accumulation chain identical to previous (bit-identical output).
// ---------------------------------------------------------------------------
__global__ __launch_bounds__(256) void proj_kernel(
    const float* __restrict__ feat, const float* __restrict__ Wp,
    const float* __restrict__ bp)
{
    __shared__ float Ws[64 * 64];
    __shared__ float Fs[16][64];
    for (int i = threadIdx.x; i < 64 * 64; i += 256) Ws[i] = Wp[i];
    int r0 = blockIdx.x * 16;
    for (int i = threadIdx.x; i < 16 * 64; i += 256)
        Fs[i >> 6][i & 63] = feat[(r0 + (i >> 6)) * 64 + (i & 63)];
    __syncthreads();
    int rr = threadIdx.x >> 6;   // 0..3
    int c  = threadIdx.x & 63;
    float a0 = bp[c], a1 = a0, a2 = a0, a3 = a0;
#pragma unroll
    for (int d = 0; d < 64; d++) {
        float w = Ws[d * 64 + c];
        a0 = fmaf(Fs[rr     ][d], w, a0);
        a1 = fmaf(Fs[rr +  4][d], w, a1);
        a2 = fmaf(Fs[rr +  8][d], w, a2);
        a3 = fmaf(Fs[rr + 12][d], w, a3);
    }
    g_f[(r0 + rr     ) * 64 + c] = a0;
    g_f[(r0 + rr +  4) * 64 + c] = a1;
    g_f[(r0 + rr +  8) * 64 + c] = a2;
    g_f[(r0 + rr + 12) * 64 + c] = a3;
}

// ---------------------------------------------------------------------------
// Kernel 2a: branchless filtered scan + append-stack, then replay through the
// original strict-< sorted insert (identical selection semantics).
// grid = (M/128, NCHUNK, B), block = 128
// ---------------------------------------------------------------------------
__global__ __launch_bounds__(128) void knn_part_kernel(
    const float* __restrict__ xyz1, const float* __restrict__ xyz2)
{
    __shared__ float4 tile[CHUNK];          // 16KB
    __shared__ float2 stk[128][CAP];        // 24KB append stacks
    int b     = blockIdx.z;
    int chunk = blockIdx.y;
    int m     = blockIdx.x * 128 + threadIdx.x;
    const float* x2 = xyz2 + ((size_t)b * M + m) * 3;
    float qx = x2[0], qy = x2[1], qz = x2[2];
    float qs = qx * qx + qy * qy + qz * qz;
    float T  = query_thresh(qx, qy, qz);

    int nbeg = chunk * CHUNK;
    const float* base = xyz1 + ((size_t)b * N + nbeg) * 3;
    for (int i = threadIdx.x; i < CHUNK; i += 128) {
        float x = base[i * 3 + 0];
        float y = base[i * 3 + 1];
        float z = base[i * 3 + 2];
        tile[i] = make_float4(x, y, z, x * x + y * y + z * z);
    }
    __syncthreads();

    float2* my = stk[threadIdx.x];
    int cnt = 0;
#pragma unroll 8
    for (int jj = 0; jj < CHUNK; jj++) {
        float4 p = tile[jj];
        float t = qx * p.x;
        t = fmaf(qy, p.y, t);
        t = fmaf(qz, p.z, t);
        float d = (qs + p.w) - 2.0f * t;   // bitwise-same formula as before
        bool pass = d < T;
        int slot = cnt < CAP ? cnt : CAP - 1;   // overwrite harmless: ovf->fallback
        if (pass) my[slot] = make_float2(d, __int_as_float(nbeg + jj));
        cnt += pass;
    }

    // replay (ascending-n order) through original strict-< sorted insert
    float bd[KNN]; int bi[KNN];
#pragma unroll
    for (int j = 0; j < KNN; j++) { bd[j] = SENT; bi[j] = 0; }
    int k = cnt < CAP ? cnt : CAP;
    for (int i = 0; i < k; i++) {
        float2 e = my[i];
        float d = e.x;
        if (d < bd[KNN - 1]) {
            bd[KNN - 1] = d; bi[KNN - 1] = __float_as_int(e.y);
#pragma unroll
            for (int j = KNN - 1; j > 0; --j) {
                if (bd[j] < bd[j - 1]) {
                    float td = bd[j]; bd[j] = bd[j - 1]; bd[j - 1] = td;
                    int   ti = bi[j]; bi[j] = bi[j - 1]; bi[j - 1] = ti;
                }
            }
        }
    }

    size_t q = (size_t)b * M + m;
    float* pd = g_pd + (q * NCHUNK + chunk) * KNN;
    int*   pi = g_pi + (q * NCHUNK + chunk) * KNN;
#pragma unroll
    for (int j = 0; j < KNN; j++) { pd[j] = bd[j]; pi[j] = bi[j]; }
    g_ovf[q * NCHUNK + chunk] = (cnt > CAP) ? 1 : 0;
}

// ---------------------------------------------------------------------------
// Kernel 2b: exact 8-way merge. Fallback to full scan if <16 passed filter
// OR any chunk stack overflowed.
// ---------------------------------------------------------------------------
__global__ __launch_bounds__(256) void knn_merge_kernel(
    const float* __restrict__ xyz1, const float* __restrict__ xyz2,
    float* __restrict__ outW)
{
    int q = blockIdx.x * 256 + threadIdx.x;
    if (q >= QTOT) return;
    const float* pd = g_pd + (size_t)q * NCHUNK * KNN;
    const int*   pi = g_pi + (size_t)q * NCHUNK * KNN;

    int ovf = 0;
#pragma unroll
    for (int c = 0; c < NCHUNK; c++) ovf |= g_ovf[(size_t)q * NCHUNK + c];

    int   ptr[NCHUNK];
    float head[NCHUNK];
#pragma unroll
    for (int c = 0; c < NCHUNK; c++) { ptr[c] = 0; head[c] = pd[c * KNN]; }

    int   outi[KNN];
    float first = SENT, last = SENT;
#pragma unroll
    for (int j = 0; j < KNN; j++) {
        int best = 0; float bv = head[0];
#pragma unroll
        for (int c = 1; c < NCHUNK; c++)
            if (head[c] < bv) { bv = head[c]; best = c; }   // earliest chunk wins ties
        outi[j] = pi[best * KNN + ptr[best]];
        if (j == 0) first = bv;
        last = bv;
        ptr[best]++;
        head[best] = (ptr[best] < KNN) ? pd[best * KNN + ptr[best]] : SENT;
    }

    if (ovf || last >= SENT) {
        // fallback: full unfiltered scan (exactness guarantee; ~never taken)
        int b = q >> 13;
        const float* x2 = xyz2 + (size_t)q * 3;
        float qx = x2[0], qy = x2[1], qz = x2[2];
        float qs = qx * qx + qy * qy + qz * qz;
        float bd[KNN];
#pragma unroll
        for (int j = 0; j < KNN; j++) { bd[j] = SENT; outi[j] = 0; }
        const float* base = xyz1 + (size_t)b * N * 3;
        for (int n = 0; n < N; n++) {
            float x = base[n * 3], y = base[n * 3 + 1], z = base[n * 3 + 2];
            float ps = x * x + y * y + z * z;
            float t = qx * x;
            t = fmaf(qy, y, t);
            t = fmaf(qz, z, t);
            float d = (qs + ps) - 2.0f * t;
            if (d < bd[KNN - 1]) {
                bd[KNN - 1] = d; outi[KNN - 1] = n;
#pragma unroll
                for (int j = KNN - 1; j > 0; --j) {
                    if (bd[j] < bd[j - 1]) {
                        float td = bd[j]; bd[j] = bd[j - 1]; bd[j - 1] = td;
                        int   ti = outi[j]; outi[j] = outi[j - 1]; outi[j - 1] = ti;
                    }
                }
            }
        }
        first = bd[0];
    }

#pragma unroll
    for (int j = 0; j < KNN; j++) g_idx[(size_t)q * KNN + j] = outi[j];
    outW[q] = (first > 0.03f) ? 10.0f : 1.0f;
}

// ---------------------------------------------------------------------------
// Kernel 3: gather + tiny MLP + weighted reduction.
// Phase 1 stages BOTH h and the gathered feature rows (Gs) in smem:
// neighbor xyz comes from lane-preloaded registers via shfl; phase 2 is pure
// FMA + LDS with no global accesses. Same values, same FMA order.
// ---------------------------------------------------------------------------
#define MLP_BLOCKS 1024         // 2048 pairs -> exactly 8 queries each
__global__ __launch_bounds__(128, 4) void mlp_kernel(
    const float* __restrict__ xyz1, const float* __restrict__ xyz2,
    const float* __restrict__ W1, const float* __restrict__ b1,
    const float* __restrict__ W2, const float* __restrict__ b2,
    float* __restrict__ out)
{
    __shared__ float Hs[2][KNN * 64];   // 8KB
    __shared__ float Gs[2][KNN * 64];   // 8KB: gathered features
    int lane = threadIdx.x & 31;
    int wid  = threadIdx.x >> 5;
    int pair = wid >> 1;                // 0..1 within block
    int c    = ((wid & 1) << 5) + lane; // my output channel 0..63

    float w2c[64];
#pragma unroll
    for (int d = 0; d < 64; d++) w2c[d] = W2[d * 64 + c];
    float w10 = W1[c], w11 = W1[64 + c], w12 = W1[128 + c];
    float b1c = b1[c], b2c = b2[c];

    float* H = Hs[pair];
    float* G = Gs[pair];
    int gp = blockIdx.x * 2 + pair;     // global pair id 0..2047

#pragma unroll 1
    for (int q = gp; q < QTOT; q += 2 * MLP_BLOCKS) {   // exactly 8 iters/pair
        int b = q >> 13;
        int j16 = (lane < KNN) ? g_idx[(size_t)q * KNN + lane] : 0;
        // lanes 0..15 preload their neighbor's coords (one latency for all 16)
        float px = 0.0f, py = 0.0f, pz = 0.0f;
        if (lane < KNN) {
            const float* p = xyz1 + ((size_t)b * N + j16) * 3;
            px = p[0]; py = p[1]; pz = p[2];
        }
        const float* x2 = xyz2 + (size_t)q * 3;
        float qx = x2[0], qy = x2[1], qz = x2[2];

        // phase 1: h + feature staging
        const float* fb = g_f + (size_t)b * N * 64;
#pragma unroll 8
        for (int k = 0; k < KNN; k++) {
            int j = __shfl_sync(0xffffffffu, j16, k);
            float gx = __shfl_sync(0xffffffffu, px, k) - qx;
            float gy = __shfl_sync(0xffffffffu, py, k) - qy;
            float gz = __shfl_sync(0xffffffffu, pz, k) - qz;
            float h = fmaf(gz, w12, fmaf(gy, w11, fmaf(gx, w10, b1c)));
            H[k * 64 + c] = fmaxf(h, 0.0f);
            G[k * 64 + c] = fb[(size_t)j * 64 + c];
        }
        __syncthreads();   // uniform count block-wide

        // phase 2: pw[c] = b2 + h . W2col ; acc += pw * gf  (no global loads)
        float acc = 0.0f;
#pragma unroll 1
        for (int k = 0; k < KNN; k++) {
            float gf = G[k * 64 + c];
            float p0 = b2c, p1 = 0.0f, p2 = 0.0f, p3 = 0.0f;
            const float4* h4 = (const float4*)(H + k * 64);
#pragma unroll
            for (int d4 = 0; d4 < 16; d4++) {
                float4 h = h4[d4];
                p0 = fmaf(h.x, w2c[4 * d4 + 0], p0);
                p1 = fmaf(h.y, w2c[4 * d4 + 1], p1);
                p2 = fmaf(h.z, w2c[4 * d4 + 2], p2);
                p3 = fmaf(h.w, w2c[4 * d4 + 3], p3);
            }
            acc = fmaf((p0 + p1) + (p2 + p3), gf, acc);
        }
        out[(size_t)q * 64 + c] = acc * 0.25f;   // 1/sqrt(16)
        __syncthreads();   // H/G reads done before next query overwrites
    }
}

// ---------------------------------------------------------------------------
// launch
// ---------------------------------------------------------------------------
extern "C" void kernel_launch(void* const* d_in, const int* in_sizes, int n_in,
                              void* d_out, int out_size)
{
    const float* feature1 = (const float*)d_in[0];
    const float* xyz1     = (const float*)d_in[1];
    const float* xyz2     = (const float*)d_in[2];
    const float* Wp       = (const float*)d_in[3];
    const float* bp       = (const float*)d_in[4];
    const float* W1       = (const float*)d_in[5];
    const float* b1       = (const float*)d_in[6];
    const float* W2       = (const float*)d_in[7];
    const float* b2       = (const float*)d_in[8];

    float* out_feat = (float*)d_out;                       // [B*M*64]
    float* out_w    = (float*)d_out + (size_t)B * M * 64;  // [B*M]

    proj_kernel<<<(B * N) / 16, 256>>>(feature1, Wp, bp);

    dim3 kg(M / 128, NCHUNK, B);
    knn_part_kernel<<<kg, 128>>>(xyz1, xyz2);
    knn_merge_kernel<<<(QTOT + 255) / 256, 256>>>(xyz1, xyz2, out_w);

    mlp_kernel<<<MLP_BLOCKS, 128>>>(xyz1, xyz2, W1, b1, W2, b2, out_feat);
}

// round 14
// speedup vs baseline: 3.7355x; 1.2477x over previous
#include <cuda_runtime.h>
#include <cuda_bf16.h>

#define B 2
#define N 8192
#define M 8192
#define D 64
#define KNN 16
#define QTOT (B * M)

#define NCHUNK 8
#define CHUNK (N / NCHUNK)     // 1024
#define CAP 24                 // per-thread append-stack capacity per chunk
#define SENT 3.4e38f
#define EPSF 5e-5f             // t-space filter margin (see proof in comments)

// Scratch (allocation-free: __device__ globals)
__device__ float g_f[B * N * D];                    // projected features, 4MB
__device__ int   g_idx[B * M * KNN];                // final knn indices
__device__ float g_pd[B * M * NCHUNK * KNN];        // partial top-16 dists
__device__ int   g_pi[B * M * NCHUNK * KNN];        // partial top-16 ids
__device__ int   g_ovf[B * M * NCHUNK];             // overflow flags

__device__ __forceinline__ unsigned long long fma2(
    unsigned long long a, unsigned long long b, unsigned long long c) {
    unsigned long long r;
    asm("fma.rn.f32x2 %0, %1, %2, %3;" : "=l"(r) : "l"(a), "l"(b), "l"(c));
    return r;
}
__device__ __forceinline__ unsigned long long pack2(float lo, float hi) {
    unsigned long long r;
    asm("mov.b64 %0, {%1, %2};" : "=l"(r) : "f"(lo), "f"(hi));
    return r;
}
__device__ __forceinline__ void unpack2(unsigned long long v, float& lo, float& hi) {
    asm("mov.b64 {%0, %1}, %2;" : "=f"(lo), "=f"(hi) : "l"(v));
}

// Per-query radius^2 threshold covering ~TARGET points in expectation.
// Performance hint only: merge kernel verifies completeness and falls back.
__device__ __forceinline__ float query_thresh(float qx, float qy, float qz) {
    const float TARGET = 48.0f;
    const float KVOL = (float)N * 4.18879f;   // N * (4/3)pi
    float r = cbrtf(TARGET / KVOL);
#pragma unroll
    for (int it = 0; it < 3; it++) {
        float inv2r = 0.5f / r;
        float fx = (fminf(qx, r) + fminf(1.0f - qx, r)) * inv2r;
        float fy = (fminf(qy, r) + fminf(1.0f - qy, r)) * inv2r;
        float fz = (fminf(qz, r) + fminf(1.0f - qz, r)) * inv2r;
        float c = fmaxf(fx * fy * fz, 0.125f);
        r = cbrtf(TARGET / (KVOL * c));
    }
    return r * r;
}

// ---------------------------------------------------------------------------
// Kernel 1: f = feature1 @ Wp + bp (16 rows/block)
// ---------------------------------------------------------------------------
__global__ __launch_bounds__(256) void proj_kernel(
    const float* __restrict__ feat, const float* __restrict__ Wp,
    const float* __restrict__ bp)
{
    __shared__ float Ws[64 * 64];
    __shared__ float Fs[16][64];
    for (int i = threadIdx.x; i < 64 * 64; i += 256) Ws[i] = Wp[i];
    int r0 = blockIdx.x * 16;
    for (int i = threadIdx.x; i < 16 * 64; i += 256)
        Fs[i >> 6][i & 63] = feat[(r0 + (i >> 6)) * 64 + (i & 63)];
    __syncthreads();
    int rr = threadIdx.x >> 6;
    int c  = threadIdx.x & 63;
    float a0 = bp[c], a1 = a0, a2 = a0, a3 = a0;
#pragma unroll
    for (int d = 0; d < 64; d++) {
        float w = Ws[d * 64 + c];
        a0 = fmaf(Fs[rr     ][d], w, a0);
        a1 = fmaf(Fs[rr +  4][d], w, a1);
        a2 = fmaf(Fs[rr +  8][d], w, a2);
        a3 = fmaf(Fs[rr + 12][d], w, a3);
    }
    g_f[(r0 + rr     ) * 64 + c] = a0;
    g_f[(r0 + rr +  4) * 64 + c] = a1;
    g_f[(r0 + rr +  8) * 64 + c] = a2;
    g_f[(r0 + rr + 12) * 64 + c] = a3;
}

// ---------------------------------------------------------------------------
// Kernel 2a: filtered scan. Hot loop compares in dot-space with margin:
//   d < T  <=>(exact)  t > 0.5*p.w + 0.5*(qs-T)
// FP rounding differs between the two forms by <~1e-6; subtracting EPSF=5e-5
// makes {d<T} a guaranteed SUBSET of passers, so the merge's sentinel check
// (<16 passers -> full-scan fallback) remains an airtight exactness guard:
// any non-passer has d > T, so if >=16 points pass, all passers outrank it.
// Stack stores indices only; d is recomputed at replay from the resident
// tile with the bitwise-original formula -> selection identical.
// grid = (M/128, NCHUNK, B), block = 128
// ---------------------------------------------------------------------------
__global__ __launch_bounds__(128) void knn_part_kernel(
    const float* __restrict__ xyz1, const float* __restrict__ xyz2)
{
    __shared__ float4 tile[CHUNK];          // 16KB
    __shared__ int    stk[128][CAP];        // 12KB index stacks
    int b     = blockIdx.z;
    int chunk = blockIdx.y;
    int m     = blockIdx.x * 128 + threadIdx.x;
    const float* x2 = xyz2 + ((size_t)b * M + m) * 3;
    float qx = x2[0], qy = x2[1], qz = x2[2];
    float qs = qx * qx + qy * qy + qz * qz;
    float T  = query_thresh(qx, qy, qz);
    float u  = 0.5f * (qs - T) - EPSF;      // folded margin

    int nbeg = chunk * CHUNK;
    const float* base = xyz1 + ((size_t)b * N + nbeg) * 3;
    for (int i = threadIdx.x; i < CHUNK; i += 128) {
        float x = base[i * 3 + 0];
        float y = base[i * 3 + 1];
        float z = base[i * 3 + 2];
        tile[i] = make_float4(x, y, z, x * x + y * y + z * z);
    }
    __syncthreads();

    int* my = stk[threadIdx.x];
    int cnt = 0;
#pragma unroll 8
    for (int jj = 0; jj < CHUNK; jj++) {
        float4 p = tile[jj];
        float t = qx * p.x;
        t = fmaf(qy, p.y, t);
        t = fmaf(qz, p.z, t);
        bool pass = t > fmaf(0.5f, p.w, u);
        int slot = cnt < CAP ? cnt : CAP - 1;   // overwrite harmless: ovf->fallback
        if (pass) my[slot] = jj;
        cnt += pass;
    }

    // replay (ascending-n order): recompute d with the ORIGINAL formula,
    // strict-< sorted insert (identical selection semantics)
    float bd[KNN]; int bi[KNN];
#pragma unroll
    for (int j = 0; j < KNN; j++) { bd[j] = SENT; bi[j] = 0; }
    int k = cnt < CAP ? cnt : CAP;
    for (int i = 0; i < k; i++) {
        int jj = my[i];
        float4 p = tile[jj];
        float t = qx * p.x;
        t = fmaf(qy, p.y, t);
        t = fmaf(qz, p.z, t);
        float d = (qs + p.w) - 2.0f * t;   // bitwise-same as original kernel
        if (d < bd[KNN - 1]) {
            bd[KNN - 1] = d; bi[KNN - 1] = nbeg + jj;
#pragma unroll
            for (int j = KNN - 1; j > 0; --j) {
                if (bd[j] < bd[j - 1]) {
                    float td = bd[j]; bd[j] = bd[j - 1]; bd[j - 1] = td;
                    int   ti = bi[j]; bi[j] = bi[j - 1]; bi[j - 1] = ti;
                }
            }
        }
    }

    size_t q = (size_t)b * M + m;
    float* pd = g_pd + (q * NCHUNK + chunk) * KNN;
    int*   pi = g_pi + (q * NCHUNK + chunk) * KNN;
#pragma unroll
    for (int j = 0; j < KNN; j++) { pd[j] = bd[j]; pi[j] = bi[j]; }
    g_ovf[q * NCHUNK + chunk] = (cnt > CAP) ? 1 : 0;
}

// ---------------------------------------------------------------------------
// Kernel 2b: exact 8-way merge; fallback to full scan on sentinel/overflow.
// ---------------------------------------------------------------------------
__global__ __launch_bounds__(256) void knn_merge_kernel(
    const float* __restrict__ xyz1, const float* __restrict__ xyz2,
    float* __restrict__ outW)
{
    int q = blockIdx.x * 256 + threadIdx.x;
    if (q >= QTOT) return;
    const float* pd = g_pd + (size_t)q * NCHUNK * KNN;
    const int*   pi = g_pi + (size_t)q * NCHUNK * KNN;

    int ovf = 0;
#pragma unroll
    for (int c = 0; c < NCHUNK; c++) ovf |= g_ovf[(size_t)q * NCHUNK + c];

    int   ptr[NCHUNK];
    float head[NCHUNK];
#pragma unroll
    for (int c = 0; c < NCHUNK; c++) { ptr[c] = 0; head[c] = pd[c * KNN]; }

    int   outi[KNN];
    float first = SENT, last = SENT;
#pragma unroll
    for (int j = 0; j < KNN; j++) {
        int best = 0; float bv = head[0];
#pragma unroll
        for (int c = 1; c < NCHUNK; c++)
            if (head[c] < bv) { bv = head[c]; best = c; }   // earliest chunk wins ties
        outi[j] = pi[best * KNN + ptr[best]];
        if (j == 0) first = bv;
        last = bv;
        ptr[best]++;
        head[best] = (ptr[best] < KNN) ? pd[best * KNN + ptr[best]] : SENT;
    }

    if (ovf || last >= SENT) {
        // fallback: full unfiltered scan (exactness guarantee; ~never taken)
        int b = q >> 13;
        const float* x2 = xyz2 + (size_t)q * 3;
        float qx = x2[0], qy = x2[1], qz = x2[2];
        float qs = qx * qx + qy * qy + qz * qz;
        float bd[KNN];
#pragma unroll
        for (int j = 0; j < KNN; j++) { bd[j] = SENT; outi[j] = 0; }
        const float* base = xyz1 + (size_t)b * N * 3;
        for (int n = 0; n < N; n++) {
            float x = base[n * 3], y = base[n * 3 + 1], z = base[n * 3 + 2];
            float ps = x * x + y * y + z * z;
            float t = qx * x;
            t = fmaf(qy, y, t);
            t = fmaf(qz, z, t);
            float d = (qs + ps) - 2.0f * t;
            if (d < bd[KNN - 1]) {
                bd[KNN - 1] = d; outi[KNN - 1] = n;
#pragma unroll
                for (int j = KNN - 1; j > 0; --j) {
                    if (bd[j] < bd[j - 1]) {
                        float td = bd[j]; bd[j] = bd[j - 1]; bd[j - 1] = td;
                        int   ti = outi[j]; outi[j] = outi[j - 1]; outi[j - 1] = ti;
                    }
                }
            }
        }
        first = bd[0];
    }

#pragma unroll
    for (int j = 0; j < KNN; j++) g_idx[(size_t)q * KNN + j] = outi[j];
    outW[q] = (first > 0.03f) ? 10.0f : 1.0f;
}

// ---------------------------------------------------------------------------
// Kernel 3: gather + MLP + reduction. ONE warp per query: lane owns channels
// (lane, lane+32); H traffic halved vs 2-warp version. Phase 2 uses packed
// fma.rn.f32x2 over d-pairs (W2 pre-packed per channel) -> FMA instr halved.
// Warp-private queries: __syncwarp only, no block barriers.
// ---------------------------------------------------------------------------
#define MLP_BLOCKS 1024         // 4096 warps -> exactly 4 queries each
__global__ __launch_bounds__(128, 3) void mlp_kernel(
    const float* __restrict__ xyz1, const float* __restrict__ xyz2,
    const float* __restrict__ W1, const float* __restrict__ b1,
    const float* __restrict__ W2, const float* __restrict__ b2,
    float* __restrict__ out)
{
    __shared__ float Hs[4][KNN * 64];   // 16KB
    __shared__ float Gs[4][KNN * 64];   // 16KB
    int lane = threadIdx.x & 31;
    int wid  = threadIdx.x >> 5;
    int ca   = lane;            // channel A
    int cb   = lane + 32;       // channel B

    // W2 packed over d-pairs, per channel: w2a[i] = (W2[2i][ca], W2[2i+1][ca])
    unsigned long long w2a[32], w2b[32];
#pragma unroll
    for (int i = 0; i < 32; i++) {
        w2a[i] = pack2(W2[(2 * i) * 64 + ca], W2[(2 * i + 1) * 64 + ca]);
        w2b[i] = pack2(W2[(2 * i) * 64 + cb], W2[(2 * i + 1) * 64 + cb]);
    }
    float w10a = W1[ca], w11a = W1[64 + ca], w12a = W1[128 + ca];
    float w10b = W1[cb], w11b = W1[64 + cb], w12b = W1[128 + cb];
    float b1a = b1[ca], b1b = b1[cb];
    float b2a = b2[ca], b2b = b2[cb];

    float* H = Hs[wid];
    float* G = Gs[wid];
    int gw = blockIdx.x * 4 + wid;

#pragma unroll 1
    for (int q = gw; q < QTOT; q += 4 * MLP_BLOCKS) {   // 4 iters/warp
        int b = q >> 13;
        int j16 = (lane < KNN) ? g_idx[(size_t)q * KNN + lane] : 0;
        float px = 0.0f, py = 0.0f, pz = 0.0f;
        if (lane < KNN) {
            const float* p = xyz1 + ((size_t)b * N + j16) * 3;
            px = p[0]; py = p[1]; pz = p[2];
        }
        const float* x2 = xyz2 + (size_t)q * 3;
        float qx = x2[0], qy = x2[1], qz = x2[2];
        const float* fb = g_f + (size_t)b * N * 64;

        // phase 1a: h channels (ca, cb) per k
#pragma unroll 8
        for (int k = 0; k < KNN; k++) {
            float gx = __shfl_sync(0xffffffffu, px, k) - qx;
            float gy = __shfl_sync(0xffffffffu, py, k) - qy;
            float gz = __shfl_sync(0xffffffffu, pz, k) - qz;
            float ha = fmaf(gz, w12a, fmaf(gy, w11a, fmaf(gx, w10a, b1a)));
            float hb = fmaf(gz, w12b, fmaf(gy, w11b, fmaf(gx, w10b, b1b)));
            H[k * 64 + ca] = fmaxf(ha, 0.0f);
            H[k * 64 + cb] = fmaxf(hb, 0.0f);
        }
        // phase 1b: gathered-feature staging (separate loop -> batched LDG)
#pragma unroll 8
        for (int k = 0; k < KNN; k++) {
            int j = __shfl_sync(0xffffffffu, j16, k);
            G[k * 64 + ca] = fb[(size_t)j * 64 + ca];
            G[k * 64 + cb] = fb[(size_t)j * 64 + cb];
        }
        __syncwarp();

        // phase 2: pw = b2 + h . W2col (packed f32x2); acc += pw * gf
        float acca = 0.0f, accb = 0.0f;
#pragma unroll 1
        for (int k = 0; k < KNN; k++) {
            float gfa = G[k * 64 + ca];
            float gfb = G[k * 64 + cb];
            const ulonglong2* h2 = (const ulonglong2*)(H + k * 64);
            unsigned long long pa0 = 0ull, pa1 = 0ull, pb0 = 0ull, pb1 = 0ull;
#pragma unroll
            for (int i = 0; i < 16; i++) {
                ulonglong2 hv = h2[i];          // (h[4i],h[4i+1]),(h[4i+2],h[4i+3])
                pa0 = fma2(hv.x, w2a[2 * i],     pa0);
                pa1 = fma2(hv.y, w2a[2 * i + 1], pa1);
                pb0 = fma2(hv.x, w2b[2 * i],     pb0);
                pb1 = fma2(hv.y, w2b[2 * i + 1], pb1);
            }
            float a0, a1, a2, a3, c0, c1, c2, c3;
            unpack2(pa0, a0, a1); unpack2(pa1, a2, a3);
            unpack2(pb0, c0, c1); unpack2(pb1, c2, c3);
            float pwa = b2a + ((a0 + a1) + (a2 + a3));
            float pwb = b2b + ((c0 + c1) + (c2 + c3));
            acca = fmaf(pwa, gfa, acca);
            accb = fmaf(pwb, gfb, accb);
        }
        out[(size_t)q * 64 + ca] = acca * 0.25f;   // 1/sqrt(16)
        out[(size_t)q * 64 + cb] = accb * 0.25f;
        __syncwarp();   // H/G reads done before next query overwrites
    }
}

// ---------------------------------------------------------------------------
// launch
// ---------------------------------------------------------------------------
extern "C" void kernel_launch(void* const* d_in, const int* in_sizes, int n_in,
                              void* d_out, int out_size)
{
    const float* feature1 = (const float*)d_in[0];
    const float* xyz1     = (const float*)d_in[1];
    const float* xyz2     = (const float*)d_in[2];
    const float* Wp       = (const float*)d_in[3];
    const float* bp       = (const float*)d_in[4];
    const float* W1       = (const float*)d_in[5];
    const float* b1       = (const float*)d_in[6];
    const float* W2       = (const float*)d_in[7];
    const float* b2       = (const float*)d_in[8];

    float* out_feat = (float*)d_out;                       // [B*M*64]
    float* out_w    = (float*)d_out + (size_t)B * M * 64;  // [B*M]

    proj_kernel<<<(B * N) / 16, 256>>>(feature1, Wp, bp);

    dim3 kg(M / 128, NCHUNK, B);
    knn_part_kernel<<<kg, 128>>>(xyz1, xyz2);
    knn_merge_kernel<<<(QTOT + 255) / 256, 256>>>(xyz1, xyz2, out_w);

    mlp_kernel<<<MLP_BLOCKS, 128>>>(xyz1, xyz2, W1, b1, W2, b2, out_feat);
}